// round 2
// baseline (speedup 1.0000x reference)
#include <cuda_runtime.h>
#include <math.h>

#define V 50257
#define E 1024
#define H 1024
#define L 52

// ---- device scratch (no allocs allowed) ----
__device__ float g_emb[H];
__device__ float g_attn[H];
__device__ float g_x[H];
__device__ float g_gi[3 * H];
__device__ float g_gh[3 * H];
__device__ float g_hnew[H];
__device__ float g_lse;

__device__ __forceinline__ float warp_reduce_sum(float v) {
#pragma unroll
    for (int o = 16; o; o >>= 1) v += __shfl_down_sync(0xffffffffu, v, o);
    return v;
}

// K1: emb = emb_table[token] @ linear_w.T + linear_b   (H rows, len E)
__global__ void __launch_bounds__(256)
k_emb_linear(const int* __restrict__ token,
             const float* __restrict__ emb_table,
             const float* __restrict__ W,
             const float* __restrict__ b) {
    __shared__ float sv[E];
    const float* erow = emb_table + (size_t)token[0] * E;
    for (int i = threadIdx.x; i < E; i += blockDim.x) sv[i] = erow[i];
    __syncthreads();
    int warp = threadIdx.x >> 5, lane = threadIdx.x & 31;
    int r = blockIdx.x * 8 + warp;
    if (r >= H) return;
    const float4* row = (const float4*)(W + (size_t)r * E);
    const float4* v4  = (const float4*)sv;
    float acc = 0.f;
#pragma unroll 8
    for (int j = lane; j < E / 4; j += 32) {
        float4 a = row[j], c = v4[j];
        acc += a.x * c.x + a.y * c.y + a.z * c.z + a.w * c.w;
    }
    acc = warp_reduce_sum(acc);
    if (lane == 0) g_emb[r] = acc + b[r];
}

// K2: attention logits (52 x 2048) + softmax + attn_applied (1024) + attn weights out
__global__ void __launch_bounds__(512)
k_attn(const float* __restrict__ hidden,
       const float* __restrict__ attn_w,
       const float* __restrict__ attn_b,
       const float* __restrict__ enc,
       float* __restrict__ out_attnw) {
    __shared__ float sv[2 * H];
    __shared__ float slog[L];
    __shared__ float sw[L];
    for (int i = threadIdx.x; i < H; i += blockDim.x) {
        sv[i]     = g_emb[i];
        sv[H + i] = hidden[i];
    }
    __syncthreads();
    int warp = threadIdx.x >> 5, lane = threadIdx.x & 31;
    const float4* v4 = (const float4*)sv;
    for (int r = warp; r < L; r += blockDim.x / 32) {
        const float4* row = (const float4*)(attn_w + (size_t)r * 2 * H);
        float acc = 0.f;
        for (int j = lane; j < (2 * H) / 4; j += 32) {
            float4 a = row[j], c = v4[j];
            acc += a.x * c.x + a.y * c.y + a.z * c.z + a.w * c.w;
        }
        acc = warp_reduce_sum(acc);
        if (lane == 0) slog[r] = acc + attn_b[r];
    }
    __syncthreads();
    if (threadIdx.x == 0) {
        float m = slog[0];
        for (int i = 1; i < L; i++) m = fmaxf(m, slog[i]);
        float s = 0.f;
        for (int i = 0; i < L; i++) { float e = expf(slog[i] - m); sw[i] = e; s += e; }
        float inv = 1.f / s;
        for (int i = 0; i < L; i++) { sw[i] *= inv; out_attnw[i] = sw[i]; }
    }
    __syncthreads();
    for (int h = threadIdx.x; h < H; h += blockDim.x) {
        float acc = 0.f;
#pragma unroll
        for (int l = 0; l < L; l++) acc += sw[l] * enc[l * H + h];
        g_attn[h] = acc;
    }
}

// K3: x = relu(comb_w @ concat(emb, attn_applied) + comb_b)  (H rows, len 2H)
__global__ void __launch_bounds__(256)
k_comb(const float* __restrict__ W, const float* __restrict__ b) {
    __shared__ float sv[2 * H];
    for (int i = threadIdx.x; i < 2 * H; i += blockDim.x) {
        sv[i] = (i < H) ? g_emb[i] : g_attn[i - H];
    }
    __syncthreads();
    int warp = threadIdx.x >> 5, lane = threadIdx.x & 31;
    int r = blockIdx.x * 8 + warp;
    if (r >= H) return;
    const float4* row = (const float4*)(W + (size_t)r * 2 * H);
    const float4* v4  = (const float4*)sv;
    float acc = 0.f;
#pragma unroll 8
    for (int j = lane; j < (2 * H) / 4; j += 32) {
        float4 a = row[j], c = v4[j];
        acc += a.x * c.x + a.y * c.y + a.z * c.z + a.w * c.w;
    }
    acc = warp_reduce_sum(acc);
    if (lane == 0) g_x[r] = fmaxf(acc + b[r], 0.f);
}

// K4: gi = gru_wih @ x + bih ; gh = gru_whh @ h0 + bhh  (3H rows each, len H)
__global__ void __launch_bounds__(256)
k_gru_gemv(const float* __restrict__ Wih, const float* __restrict__ Whh,
           const float* __restrict__ bih, const float* __restrict__ bhh,
           const float* __restrict__ hidden) {
    __shared__ float sx[H];
    __shared__ float sh[H];
    for (int i = threadIdx.x; i < H; i += blockDim.x) {
        sx[i] = g_x[i];
        sh[i] = hidden[i];
    }
    __syncthreads();
    int warp = threadIdx.x >> 5, lane = threadIdx.x & 31;
    int r = blockIdx.x * 8 + warp;
    if (r >= 3 * H) return;
    const float4* ri = (const float4*)(Wih + (size_t)r * H);
    const float4* rh = (const float4*)(Whh + (size_t)r * H);
    const float4* x4 = (const float4*)sx;
    const float4* h4 = (const float4*)sh;
    float ai = 0.f, ah = 0.f;
#pragma unroll 4
    for (int j = lane; j < H / 4; j += 32) {
        float4 a = ri[j], c = x4[j];
        ai += a.x * c.x + a.y * c.y + a.z * c.z + a.w * c.w;
        float4 bx = rh[j], d = h4[j];
        ah += bx.x * d.x + bx.y * d.y + bx.z * d.z + bx.w * d.w;
    }
    ai = warp_reduce_sum(ai);
    ah = warp_reduce_sum(ah);
    if (lane == 0) { g_gi[r] = ai + bih[r]; g_gh[r] = ah + bhh[r]; }
}

// K5: GRU cell combine -> h_new (also written into output slot)
__global__ void __launch_bounds__(256)
k_gru_combine(const float* __restrict__ hidden, float* __restrict__ out_h) {
    int i = blockIdx.x * blockDim.x + threadIdx.x;
    if (i >= H) return;
    float ir = g_gi[i], iz = g_gi[H + i], inn = g_gi[2 * H + i];
    float hr = g_gh[i], hz = g_gh[H + i], hn = g_gh[2 * H + i];
    float r = 1.f / (1.f + expf(-(ir + hr)));
    float z = 1.f / (1.f + expf(-(iz + hz)));
    float n = tanhf(inn + r * hn);
    float hv = (1.f - z) * n + z * hidden[i];
    g_hnew[i] = hv;
    out_h[i] = hv;
}

// K6: logits = out_w @ h_new + out_b  (V rows, len H) — the 206 MB streamer
__global__ void __launch_bounds__(256)
k_out(const float* __restrict__ W, const float* __restrict__ b,
      float* __restrict__ out) {
    __shared__ float sv[H];
    for (int i = threadIdx.x; i < H; i += blockDim.x) sv[i] = g_hnew[i];
    __syncthreads();
    int warp = threadIdx.x >> 5, lane = threadIdx.x & 31;
    int r = blockIdx.x * 8 + warp;
    if (r >= V) return;
    const float4* row = (const float4*)(W + (size_t)r * H);
    const float4* v4  = (const float4*)sv;
    float acc = 0.f;
#pragma unroll 8
    for (int j = lane; j < H / 4; j += 32) {
        float4 a = row[j], c = v4[j];
        acc += a.x * c.x + a.y * c.y + a.z * c.z + a.w * c.w;
    }
    acc = warp_reduce_sum(acc);
    if (lane == 0) out[r] = acc + b[r];
}

// K7: single-block logsumexp over logits (V floats, L2-resident)
__global__ void __launch_bounds__(512)
k_lse(const float* __restrict__ logits) {
    __shared__ float red[32];
    int warp = threadIdx.x >> 5, lane = threadIdx.x & 31;
    int nwarp = blockDim.x >> 5;

    float m = -INFINITY;
    for (int i = threadIdx.x; i < V; i += blockDim.x) m = fmaxf(m, logits[i]);
#pragma unroll
    for (int o = 16; o; o >>= 1) m = fmaxf(m, __shfl_down_sync(0xffffffffu, m, o));
    if (lane == 0) red[warp] = m;
    __syncthreads();
    if (warp == 0) {
        float t = (lane < nwarp) ? red[lane] : -INFINITY;
#pragma unroll
        for (int o = 16; o; o >>= 1) t = fmaxf(t, __shfl_down_sync(0xffffffffu, t, o));
        if (lane == 0) red[0] = t;
    }
    __syncthreads();
    m = red[0];
    __syncthreads();

    float s = 0.f;
    for (int i = threadIdx.x; i < V; i += blockDim.x) s += expf(logits[i] - m);
    s = warp_reduce_sum(s);
    if (lane == 0) red[warp] = s;
    __syncthreads();
    if (warp == 0) {
        float t = (lane < nwarp) ? red[lane] : 0.f;
        t = warp_reduce_sum(t);
        if (lane == 0) g_lse = m + logf(t);
    }
}

// K8: log_probs = logits - lse (in place)
__global__ void __launch_bounds__(256)
k_sub(float* __restrict__ out) {
    int i = blockIdx.x * blockDim.x + threadIdx.x;
    if (i < V) out[i] -= g_lse;
}

extern "C" void kernel_launch(void* const* d_in, const int* in_sizes, int n_in,
                              void* d_out, int out_size) {
    const int*   token     = (const int*)d_in[0];
    const float* hidden    = (const float*)d_in[1];
    const float* enc       = (const float*)d_in[2];
    const float* emb_table = (const float*)d_in[3];
    const float* linear_w  = (const float*)d_in[4];
    const float* linear_b  = (const float*)d_in[5];
    const float* attn_w    = (const float*)d_in[6];
    const float* attn_b    = (const float*)d_in[7];
    const float* comb_w    = (const float*)d_in[8];
    const float* comb_b    = (const float*)d_in[9];
    const float* gru_wih   = (const float*)d_in[10];
    const float* gru_whh   = (const float*)d_in[11];
    const float* gru_bih   = (const float*)d_in[12];
    const float* gru_bhh   = (const float*)d_in[13];
    const float* out_w     = (const float*)d_in[14];
    const float* out_b     = (const float*)d_in[15];

    float* out   = (float*)d_out;         // [0,V) log_probs
    float* out_h = out + V;               // [V, V+H) h_new
    float* out_aw = out + V + H;          // [V+H, V+H+L) attn weights

    k_emb_linear<<<(H + 7) / 8, 256>>>(token, emb_table, linear_w, linear_b);
    k_attn<<<1, 512>>>(hidden, attn_w, attn_b, enc, out_aw);
    k_comb<<<(H + 7) / 8, 256>>>(comb_w, comb_b);
    k_gru_gemv<<<(3 * H + 7) / 8, 256>>>(gru_wih, gru_whh, gru_bih, gru_bhh, hidden);
    k_gru_combine<<<(H + 255) / 256, 256>>>(hidden, out_h);
    k_out<<<(V + 7) / 8, 256>>>(out_w, out_b, out);
    k_lse<<<1, 512>>>(out);
    k_sub<<<(V + 255) / 256, 256>>>(out);
}

// round 3
// speedup vs baseline: 1.0567x; 1.0567x over previous
#include <cuda_runtime.h>
#include <math.h>

#define V 50257
#define E 1024
#define H 1024
#define L 52

#define OUT_BLOCKS 786   /* 786 blocks * 8 warps * 8 rows = 50304 >= V */

// ---- device scratch (no allocs allowed) ----
__device__ float g_emb[H];
__device__ float g_attn[H];
__device__ float g_x[H];
__device__ float g_gi[3 * H];
__device__ float g_gh[3 * H];
__device__ float g_hnew[H];
__device__ float2 g_ms[OUT_BLOCKS];   // per-block online (max, sumexp)

__device__ __forceinline__ float warp_reduce_sum(float v) {
#pragma unroll
    for (int o = 16; o; o >>= 1) v += __shfl_down_sync(0xffffffffu, v, o);
    return v;
}

// online-softmax pair merge: (m,s) <- (m,s) (+) (m2,s2)
__device__ __forceinline__ void ms_merge(float& m, float& s, float m2, float s2) {
    if (s2 == 0.f) return;
    if (s == 0.f) { m = m2; s = s2; return; }
    float M = fmaxf(m, m2);
    s = s * expf(m - M) + s2 * expf(m2 - M);
    m = M;
}

// K1: emb = emb_table[token] @ linear_w.T + linear_b   (H rows, len E)
__global__ void __launch_bounds__(256)
k_emb_linear(const int* __restrict__ token,
             const float* __restrict__ emb_table,
             const float* __restrict__ W,
             const float* __restrict__ b) {
    __shared__ float sv[E];
    const float* erow = emb_table + (size_t)token[0] * E;
    for (int i = threadIdx.x; i < E; i += blockDim.x) sv[i] = erow[i];
    __syncthreads();
    int warp = threadIdx.x >> 5, lane = threadIdx.x & 31;
    int r = blockIdx.x * 8 + warp;
    if (r >= H) return;
    const float4* row = (const float4*)(W + (size_t)r * E);
    const float4* v4  = (const float4*)sv;
    float acc = 0.f;
#pragma unroll 8
    for (int j = lane; j < E / 4; j += 32) {
        float4 a = row[j], c = v4[j];
        acc += a.x * c.x + a.y * c.y + a.z * c.z + a.w * c.w;
    }
    acc = warp_reduce_sum(acc);
    if (lane == 0) g_emb[r] = acc + b[r];
}

// K2: attention logits (52 x 2048) + softmax + attn_applied + attn weights out
__global__ void __launch_bounds__(512)
k_attn(const float* __restrict__ hidden,
       const float* __restrict__ attn_w,
       const float* __restrict__ attn_b,
       const float* __restrict__ enc,
       float* __restrict__ out_attnw) {
    __shared__ float sv[2 * H];
    __shared__ float slog[L];
    __shared__ float sw[L];
    for (int i = threadIdx.x; i < H; i += blockDim.x) {
        sv[i]     = g_emb[i];
        sv[H + i] = hidden[i];
    }
    __syncthreads();
    int warp = threadIdx.x >> 5, lane = threadIdx.x & 31;
    const float4* v4 = (const float4*)sv;
    for (int r = warp; r < L; r += blockDim.x / 32) {
        const float4* row = (const float4*)(attn_w + (size_t)r * 2 * H);
        float acc = 0.f;
        for (int j = lane; j < (2 * H) / 4; j += 32) {
            float4 a = row[j], c = v4[j];
            acc += a.x * c.x + a.y * c.y + a.z * c.z + a.w * c.w;
        }
        acc = warp_reduce_sum(acc);
        if (lane == 0) slog[r] = acc + attn_b[r];
    }
    __syncthreads();
    if (threadIdx.x == 0) {
        float m = slog[0];
        for (int i = 1; i < L; i++) m = fmaxf(m, slog[i]);
        float s = 0.f;
        for (int i = 0; i < L; i++) { float e = expf(slog[i] - m); sw[i] = e; s += e; }
        float inv = 1.f / s;
        for (int i = 0; i < L; i++) { sw[i] *= inv; out_attnw[i] = sw[i]; }
    }
    __syncthreads();
    for (int h = threadIdx.x; h < H; h += blockDim.x) {
        float acc = 0.f;
#pragma unroll
        for (int l = 0; l < L; l++) acc += sw[l] * enc[l * H + h];
        g_attn[h] = acc;
    }
}

// K3: x = relu(comb_w @ concat(emb, attn) + comb_b)  (H rows, len 2H)
__global__ void __launch_bounds__(256)
k_comb(const float* __restrict__ W, const float* __restrict__ b) {
    __shared__ float sv[2 * H];
    for (int i = threadIdx.x; i < 2 * H; i += blockDim.x) {
        sv[i] = (i < H) ? g_emb[i] : g_attn[i - H];
    }
    __syncthreads();
    int warp = threadIdx.x >> 5, lane = threadIdx.x & 31;
    int r = blockIdx.x * 8 + warp;
    if (r >= H) return;
    const float4* row = (const float4*)(W + (size_t)r * 2 * H);
    const float4* v4  = (const float4*)sv;
    float acc = 0.f;
#pragma unroll 8
    for (int j = lane; j < (2 * H) / 4; j += 32) {
        float4 a = row[j], c = v4[j];
        acc += a.x * c.x + a.y * c.y + a.z * c.z + a.w * c.w;
    }
    acc = warp_reduce_sum(acc);
    if (lane == 0) g_x[r] = fmaxf(acc + b[r], 0.f);
}

// K4: 6144 row-tasks: t<3H -> gi row t (Wih @ x), else gh row t-3H (Whh @ h0).
// 2 tasks per warp; pairs never straddle the 3H boundary (3H even).
__global__ void __launch_bounds__(256)
k_gru_gemv(const float* __restrict__ Wih, const float* __restrict__ Whh,
           const float* __restrict__ bih, const float* __restrict__ bhh,
           const float* __restrict__ hidden) {
    __shared__ float sx[H];
    __shared__ float sh[H];
    for (int i = threadIdx.x; i < H; i += blockDim.x) {
        sx[i] = g_x[i];
        sh[i] = hidden[i];
    }
    __syncthreads();
    int warp = threadIdx.x >> 5, lane = threadIdx.x & 31;
    int t0 = (blockIdx.x * 8 + warp) * 2;          // 0..6142
    bool is_ih = (t0 < 3 * H);
    int r0 = is_ih ? t0 : t0 - 3 * H;
    const float* Wm = is_ih ? Wih : Whh;
    const float4* row0 = (const float4*)(Wm + (size_t)r0 * H);
    const float4* row1 = (const float4*)(Wm + (size_t)(r0 + 1) * H);
    const float4* v4 = (const float4*)(is_ih ? sx : sh);
    float a0 = 0.f, a1 = 0.f;
#pragma unroll 8
    for (int j = lane; j < H / 4; j += 32) {
        float4 c = v4[j];
        float4 x = row0[j];
        float4 y = row1[j];
        a0 += x.x * c.x + x.y * c.y + x.z * c.z + x.w * c.w;
        a1 += y.x * c.x + y.y * c.y + y.z * c.z + y.w * c.w;
    }
    a0 = warp_reduce_sum(a0);
    a1 = warp_reduce_sum(a1);
    if (lane == 0) {
        if (is_ih) { g_gi[r0] = a0 + bih[r0]; g_gi[r0 + 1] = a1 + bih[r0 + 1]; }
        else       { g_gh[r0] = a0 + bhh[r0]; g_gh[r0 + 1] = a1 + bhh[r0 + 1]; }
    }
}

// K5: GRU cell combine -> h_new (also written into output slot)
__global__ void __launch_bounds__(256)
k_gru_combine(const float* __restrict__ hidden, float* __restrict__ out_h) {
    int i = blockIdx.x * blockDim.x + threadIdx.x;
    if (i >= H) return;
    float ir = g_gi[i], iz = g_gi[H + i], inn = g_gi[2 * H + i];
    float hr = g_gh[i], hz = g_gh[H + i], hn = g_gh[2 * H + i];
    float r = 1.f / (1.f + expf(-(ir + hr)));
    float z = 1.f / (1.f + expf(-(iz + hz)));
    float n = tanhf(inn + r * hn);
    float hv = (1.f - z) * n + z * hidden[i];
    g_hnew[i] = hv;
    out_h[i] = hv;
}

// K6: logits = out_w @ h_new + out_b. 8 contiguous rows per warp, processed in
// pairs (16 interleaved LDG.128). Each block emits an online (max,sumexp) pair.
__global__ void __launch_bounds__(256)
k_out(const float* __restrict__ W, const float* __restrict__ b,
      float* __restrict__ out) {
    __shared__ float sv[H];
    __shared__ float wm[8], ws[8];
    for (int i = threadIdx.x; i < H; i += blockDim.x) sv[i] = g_hnew[i];
    __syncthreads();
    int warp = threadIdx.x >> 5, lane = threadIdx.x & 31;
    const float4* v4 = (const float4*)sv;
    int base = (blockIdx.x * 8 + warp) * 8;        // 8 contiguous rows per warp
    float m_w = -INFINITY, s_w = 0.f;
#pragma unroll
    for (int pr = 0; pr < 4; pr++) {
        int r0 = base + 2 * pr;
        if (r0 >= V) break;
        int r1c = min(r0 + 1, V - 1);              // clamp; duplicate read harmless
        const float4* row0 = (const float4*)(W + (size_t)r0 * H);
        const float4* row1 = (const float4*)(W + (size_t)r1c * H);
        float a0 = 0.f, a1 = 0.f;
#pragma unroll 8
        for (int j = lane; j < H / 4; j += 32) {
            float4 c = v4[j];
            float4 x = row0[j];
            float4 y = row1[j];
            a0 += x.x * c.x + x.y * c.y + x.z * c.z + x.w * c.w;
            a1 += y.x * c.x + y.y * c.y + y.z * c.z + y.w * c.w;
        }
        a0 = warp_reduce_sum(a0);
        a1 = warp_reduce_sum(a1);
        if (lane == 0) {
            float l0 = a0 + b[r0];
            out[r0] = l0;
            ms_merge(m_w, s_w, l0, 1.f);
            if (r0 + 1 < V) {
                float l1 = a1 + b[r0 + 1];
                out[r0 + 1] = l1;
                ms_merge(m_w, s_w, l1, 1.f);
            }
        }
    }
    if (lane == 0) { wm[warp] = m_w; ws[warp] = s_w; }
    __syncthreads();
    if (threadIdx.x == 0) {
        float m = -INFINITY, s = 0.f;
#pragma unroll
        for (int w = 0; w < 8; w++) ms_merge(m, s, wm[w], ws[w]);
        g_ms[blockIdx.x] = make_float2(m, s);
    }
}

// K7: merge per-block (m,s) pairs -> lse, then subtract (log_softmax in place)
__global__ void __launch_bounds__(256)
k_sub(float* __restrict__ out) {
    __shared__ float sm[256], ss[256];
    float m = -INFINITY, s = 0.f;
    for (int i = threadIdx.x; i < OUT_BLOCKS; i += 256) {
        float2 p = g_ms[i];
        ms_merge(m, s, p.x, p.y);
    }
    sm[threadIdx.x] = m; ss[threadIdx.x] = s;
    __syncthreads();
    for (int st = 128; st; st >>= 1) {
        if (threadIdx.x < st) {
            float m1 = sm[threadIdx.x], s1 = ss[threadIdx.x];
            ms_merge(m1, s1, sm[threadIdx.x + st], ss[threadIdx.x + st]);
            sm[threadIdx.x] = m1; ss[threadIdx.x] = s1;
        }
        __syncthreads();
    }
    float lse = sm[0] + logf(ss[0]);
    for (int i = blockIdx.x * 256 + threadIdx.x; i < V; i += gridDim.x * 256)
        out[i] -= lse;
}

extern "C" void kernel_launch(void* const* d_in, const int* in_sizes, int n_in,
                              void* d_out, int out_size) {
    const int*   token     = (const int*)d_in[0];
    const float* hidden    = (const float*)d_in[1];
    const float* enc       = (const float*)d_in[2];
    const float* emb_table = (const float*)d_in[3];
    const float* linear_w  = (const float*)d_in[4];
    const float* linear_b  = (const float*)d_in[5];
    const float* attn_w    = (const float*)d_in[6];
    const float* attn_b    = (const float*)d_in[7];
    const float* comb_w    = (const float*)d_in[8];
    const float* comb_b    = (const float*)d_in[9];
    const float* gru_wih   = (const float*)d_in[10];
    const float* gru_whh   = (const float*)d_in[11];
    const float* gru_bih   = (const float*)d_in[12];
    const float* gru_bhh   = (const float*)d_in[13];
    const float* out_w     = (const float*)d_in[14];
    const float* out_b     = (const float*)d_in[15];

    float* out    = (float*)d_out;        // [0,V) log_probs
    float* out_h  = out + V;              // [V, V+H) h_new
    float* out_aw = out + V + H;          // [V+H, V+H+L) attn weights

    k_emb_linear<<<(H + 7) / 8, 256>>>(token, emb_table, linear_w, linear_b);
    k_attn<<<1, 512>>>(hidden, attn_w, attn_b, enc, out_aw);
    k_comb<<<(H + 7) / 8, 256>>>(comb_w, comb_b);
    k_gru_gemv<<<384, 256>>>(gru_wih, gru_whh, gru_bih, gru_bhh, hidden);
    k_gru_combine<<<(H + 255) / 256, 256>>>(hidden, out_h);
    k_out<<<OUT_BLOCKS, 256>>>(out_w, out_b, out);
    k_sub<<<148, 256>>>(out);
}

// round 4
// speedup vs baseline: 1.7630x; 1.6684x over previous
#include <cuda_runtime.h>
#include <math.h>

#define V 50257
#define E 1024
#define H 1024
#define L 52

#define OUT_BLOCKS 786   /* 786 blocks * 8 warps * 8 rows = 50304 >= V */

// ---- device scratch (no allocs allowed) ----
__device__ float g_emb[H];
__device__ float g_attn[H];
__device__ float g_x[H];
__device__ float g_alog[L];
__device__ float g_gi[3 * H];
__device__ float g_gh[3 * H];
__device__ float g_hnew[H];
__device__ float2 g_ms[OUT_BLOCKS];   // per-block online (max, sumexp)
__device__ int   g_cnt;               // zero-init; reset by last block each launch

__device__ __forceinline__ float warp_reduce_sum(float v) {
#pragma unroll
    for (int o = 16; o; o >>= 1) v += __shfl_down_sync(0xffffffffu, v, o);
    return v;
}

// online-softmax pair merge: (m,s) <- (m,s) (+) (m2,s2)
__device__ __forceinline__ void ms_merge(float& m, float& s, float m2, float s2) {
    if (s2 == 0.f) return;
    if (s == 0.f) { m = m2; s = s2; return; }
    float M = fmaxf(m, m2);
    s = s * expf(m - M) + s2 * expf(m2 - M);
    m = M;
}

// Dot of TWO weight rows against a shared vector, front-batched:
// NF4 float4-chunks per lane per row, processed in groups of 8 so that
// 16 LDG.128 are in flight before the first FMA.
template <int NF4>
__device__ __forceinline__ void dot2rows(const float4* __restrict__ row0,
                                         const float4* __restrict__ row1,
                                         const float4* __restrict__ v4,
                                         int lane, float& a0, float& a1) {
#pragma unroll
    for (int g = 0; g < NF4 / 8; g++) {
        float4 xa[8], ya[8];
#pragma unroll
        for (int u = 0; u < 8; u++) {
            int j = lane + (g * 8 + u) * 32;
            xa[u] = row0[j];
            ya[u] = row1[j];
        }
#pragma unroll
        for (int u = 0; u < 8; u++) {
            int j = lane + (g * 8 + u) * 32;
            float4 c = v4[j];
            a0 += xa[u].x * c.x + xa[u].y * c.y + xa[u].z * c.z + xa[u].w * c.w;
            a1 += ya[u].x * c.x + ya[u].y * c.y + ya[u].z * c.z + ya[u].w * c.w;
        }
    }
}

// K1: emb = emb_table[token] @ linear_w.T + linear_b   (H rows, len E)
// 2 rows per warp -> 64 blocks * 8 warps * 2 = 1024
__global__ void __launch_bounds__(256, 2)
k_emb_linear(const int* __restrict__ token,
             const float* __restrict__ emb_table,
             const float* __restrict__ W,
             const float* __restrict__ b) {
    __shared__ float sv[E];
    const float* erow = emb_table + (size_t)token[0] * E;
    for (int i = threadIdx.x; i < E; i += blockDim.x) sv[i] = erow[i];
    __syncthreads();
    int warp = threadIdx.x >> 5, lane = threadIdx.x & 31;
    int r0 = (blockIdx.x * 8 + warp) * 2;
    const float4* row0 = (const float4*)(W + (size_t)r0 * E);
    const float4* row1 = (const float4*)(W + (size_t)(r0 + 1) * E);
    float a0 = 0.f, a1 = 0.f;
    dot2rows<8>(row0, row1, (const float4*)sv, lane, a0, a1);
    a0 = warp_reduce_sum(a0);
    a1 = warp_reduce_sum(a1);
    if (lane == 0) {
        g_emb[r0]     = a0 + b[r0];
        g_emb[r0 + 1] = a1 + b[r0 + 1];
    }
}

// K2a: attention logits: 52 rows of length 2H. 2 rows/warp -> 26 warps -> 4 blocks.
__global__ void __launch_bounds__(256, 2)
k_attn_logits(const float* __restrict__ hidden,
              const float* __restrict__ attn_w,
              const float* __restrict__ attn_b) {
    __shared__ float sv[2 * H];
    for (int i = threadIdx.x; i < H; i += blockDim.x) {
        sv[i]     = g_emb[i];
        sv[H + i] = hidden[i];
    }
    __syncthreads();
    int warp = threadIdx.x >> 5, lane = threadIdx.x & 31;
    int r0 = (blockIdx.x * 8 + warp) * 2;
    if (r0 >= L) return;
    const float4* row0 = (const float4*)(attn_w + (size_t)r0 * 2 * H);
    const float4* row1 = (const float4*)(attn_w + (size_t)(r0 + 1) * 2 * H);
    float a0 = 0.f, a1 = 0.f;
    dot2rows<16>(row0, row1, (const float4*)sv, lane, a0, a1);
    a0 = warp_reduce_sum(a0);
    a1 = warp_reduce_sum(a1);
    if (lane == 0) {
        g_alog[r0]     = a0 + attn_b[r0];
        g_alog[r0 + 1] = a1 + attn_b[r0 + 1];
    }
}

// K2b: softmax over 52 logits (redundant per block) + attn_applied slice.
// 4 blocks * 256 cols. Block 0 also writes attn weights to output.
__global__ void __launch_bounds__(256)
k_attn_apply(const float* __restrict__ enc, float* __restrict__ out_attnw) {
    __shared__ float sw[L];
    if (threadIdx.x == 0) {
        float m = g_alog[0];
        for (int i = 1; i < L; i++) m = fmaxf(m, g_alog[i]);
        float s = 0.f;
        for (int i = 0; i < L; i++) { float e = expf(g_alog[i] - m); sw[i] = e; s += e; }
        float inv = 1.f / s;
        for (int i = 0; i < L; i++) sw[i] *= inv;
    }
    __syncthreads();
    int h = blockIdx.x * 256 + threadIdx.x;
    float acc = 0.f;
#pragma unroll
    for (int l = 0; l < L; l++) acc += sw[l] * enc[l * H + h];
    g_attn[h] = acc;
    if (blockIdx.x == 0 && threadIdx.x < L) out_attnw[threadIdx.x] = sw[threadIdx.x];
}

// K3: x = relu(comb_w @ concat(emb, attn) + comb_b)  (H rows, len 2H), 2 rows/warp
__global__ void __launch_bounds__(256, 2)
k_comb(const float* __restrict__ W, const float* __restrict__ b) {
    __shared__ float sv[2 * H];
    for (int i = threadIdx.x; i < H; i += blockDim.x) {
        sv[i]     = g_emb[i];
        sv[H + i] = g_attn[i];
    }
    __syncthreads();
    int warp = threadIdx.x >> 5, lane = threadIdx.x & 31;
    int r0 = (blockIdx.x * 8 + warp) * 2;
    const float4* row0 = (const float4*)(W + (size_t)r0 * 2 * H);
    const float4* row1 = (const float4*)(W + (size_t)(r0 + 1) * 2 * H);
    float a0 = 0.f, a1 = 0.f;
    dot2rows<16>(row0, row1, (const float4*)sv, lane, a0, a1);
    a0 = warp_reduce_sum(a0);
    a1 = warp_reduce_sum(a1);
    if (lane == 0) {
        g_x[r0]     = fmaxf(a0 + b[r0], 0.f);
        g_x[r0 + 1] = fmaxf(a1 + b[r0 + 1], 0.f);
    }
}

// K4: gi/gh GEMVs (6144 row-tasks, 2 per warp) + fused GRU combine in the
// last-finishing block (atomic counter; deterministic; self-resetting).
__global__ void __launch_bounds__(256, 2)
k_gru(const float* __restrict__ Wih, const float* __restrict__ Whh,
      const float* __restrict__ bih, const float* __restrict__ bhh,
      const float* __restrict__ hidden, float* __restrict__ out_h) {
    __shared__ float sx[H];
    __shared__ float sh[H];
    __shared__ int slast;
    for (int i = threadIdx.x; i < H; i += blockDim.x) {
        sx[i] = g_x[i];
        sh[i] = hidden[i];
    }
    __syncthreads();
    int warp = threadIdx.x >> 5, lane = threadIdx.x & 31;
    int t0 = (blockIdx.x * 8 + warp) * 2;          // 0..6142, never straddles 3H
    bool is_ih = (t0 < 3 * H);
    int r0 = is_ih ? t0 : t0 - 3 * H;
    const float* Wm = is_ih ? Wih : Whh;
    const float4* row0 = (const float4*)(Wm + (size_t)r0 * H);
    const float4* row1 = (const float4*)(Wm + (size_t)(r0 + 1) * H);
    const float4* v4 = (const float4*)(is_ih ? sx : sh);
    float a0 = 0.f, a1 = 0.f;
    dot2rows<8>(row0, row1, v4, lane, a0, a1);
    a0 = warp_reduce_sum(a0);
    a1 = warp_reduce_sum(a1);
    if (lane == 0) {
        if (is_ih) { g_gi[r0] = a0 + bih[r0]; g_gi[r0 + 1] = a1 + bih[r0 + 1]; }
        else       { g_gh[r0] = a0 + bhh[r0]; g_gh[r0 + 1] = a1 + bhh[r0 + 1]; }
    }
    // ---- last-block-done fused combine ----
    __syncthreads();
    __threadfence();
    if (threadIdx.x == 0) {
        int p = atomicAdd(&g_cnt, 1);
        slast = (p == (int)gridDim.x - 1);
    }
    __syncthreads();
    if (slast) {
        __threadfence();
        for (int i = threadIdx.x; i < H; i += blockDim.x) {
            float ir = g_gi[i], iz = g_gi[H + i], inn = g_gi[2 * H + i];
            float hr = g_gh[i], hz = g_gh[H + i], hn = g_gh[2 * H + i];
            float r = 1.f / (1.f + expf(-(ir + hr)));
            float z = 1.f / (1.f + expf(-(iz + hz)));
            float n = tanhf(inn + r * hn);
            float hv = (1.f - z) * n + z * sh[i];
            g_hnew[i] = hv;
            out_h[i] = hv;
        }
        if (threadIdx.x == 0) g_cnt = 0;   // reset for next replay
    }
}

// K5: logits = out_w @ h_new + out_b. 8 contiguous rows per warp, in 4
// front-batched pairs. Each block emits an online (max,sumexp) pair.
__global__ void __launch_bounds__(256, 2)
k_out(const float* __restrict__ W, const float* __restrict__ b,
      float* __restrict__ out) {
    __shared__ float sv[H];
    __shared__ float wm[8], ws[8];
    for (int i = threadIdx.x; i < H; i += blockDim.x) sv[i] = g_hnew[i];
    __syncthreads();
    int warp = threadIdx.x >> 5, lane = threadIdx.x & 31;
    const float4* v4 = (const float4*)sv;
    int base = (blockIdx.x * 8 + warp) * 8;
    float m_w = -INFINITY, s_w = 0.f;
#pragma unroll
    for (int pr = 0; pr < 4; pr++) {
        int r0 = base + 2 * pr;
        if (r0 >= V) break;
        int r1c = min(r0 + 1, V - 1);              // clamp; duplicate read harmless
        const float4* row0 = (const float4*)(W + (size_t)r0 * H);
        const float4* row1 = (const float4*)(W + (size_t)r1c * H);
        float a0 = 0.f, a1 = 0.f;
        dot2rows<8>(row0, row1, v4, lane, a0, a1);
        a0 = warp_reduce_sum(a0);
        a1 = warp_reduce_sum(a1);
        if (lane == 0) {
            float l0 = a0 + b[r0];
            out[r0] = l0;
            ms_merge(m_w, s_w, l0, 1.f);
            if (r0 + 1 < V) {
                float l1 = a1 + b[r0 + 1];
                out[r0 + 1] = l1;
                ms_merge(m_w, s_w, l1, 1.f);
            }
        }
    }
    if (lane == 0) { wm[warp] = m_w; ws[warp] = s_w; }
    __syncthreads();
    if (threadIdx.x == 0) {
        float m = -INFINITY, s = 0.f;
#pragma unroll
        for (int w = 0; w < 8; w++) ms_merge(m, s, wm[w], ws[w]);
        g_ms[blockIdx.x] = make_float2(m, s);
    }
}

// K6: merge per-block (m,s) pairs -> lse, then subtract (log_softmax in place)
__global__ void __launch_bounds__(256)
k_sub(float* __restrict__ out) {
    __shared__ float sm[256], ss[256];
    float m = -INFINITY, s = 0.f;
    for (int i = threadIdx.x; i < OUT_BLOCKS; i += 256) {
        float2 p = g_ms[i];
        ms_merge(m, s, p.x, p.y);
    }
    sm[threadIdx.x] = m; ss[threadIdx.x] = s;
    __syncthreads();
    for (int st = 128; st; st >>= 1) {
        if (threadIdx.x < st) {
            float m1 = sm[threadIdx.x], s1 = ss[threadIdx.x];
            ms_merge(m1, s1, sm[threadIdx.x + st], ss[threadIdx.x + st]);
            sm[threadIdx.x] = m1; ss[threadIdx.x] = s1;
        }
        __syncthreads();
    }
    float lse = sm[0] + logf(ss[0]);
    for (int i = blockIdx.x * 256 + threadIdx.x; i < V; i += gridDim.x * 256)
        out[i] -= lse;
}

extern "C" void kernel_launch(void* const* d_in, const int* in_sizes, int n_in,
                              void* d_out, int out_size) {
    const int*   token     = (const int*)d_in[0];
    const float* hidden    = (const float*)d_in[1];
    const float* enc       = (const float*)d_in[2];
    const float* emb_table = (const float*)d_in[3];
    const float* linear_w  = (const float*)d_in[4];
    const float* linear_b  = (const float*)d_in[5];
    const float* attn_w    = (const float*)d_in[6];
    const float* attn_b    = (const float*)d_in[7];
    const float* comb_w    = (const float*)d_in[8];
    const float* comb_b    = (const float*)d_in[9];
    const float* gru_wih   = (const float*)d_in[10];
    const float* gru_whh   = (const float*)d_in[11];
    const float* gru_bih   = (const float*)d_in[12];
    const float* gru_bhh   = (const float*)d_in[13];
    const float* out_w     = (const float*)d_in[14];
    const float* out_b     = (const float*)d_in[15];

    float* out    = (float*)d_out;        // [0,V) log_probs
    float* out_h  = out + V;              // [V, V+H) h_new
    float* out_aw = out + V + H;          // [V+H, V+H+L) attn weights

    k_emb_linear<<<64, 256>>>(token, emb_table, linear_w, linear_b);     // 1
    k_attn_logits<<<4, 256>>>(hidden, attn_w, attn_b);                   // 2
    k_attn_apply<<<4, 256>>>(enc, out_aw);                               // 3
    k_comb<<<64, 256>>>(comb_w, comb_b);                                 // 4
    k_gru<<<384, 256>>>(gru_wih, gru_whh, gru_bih, gru_bhh, hidden, out_h); // 5
    k_out<<<OUT_BLOCKS, 256>>>(out_w, out_b, out);                       // 6 (ncu slot)
    k_sub<<<200, 256>>>(out);                                            // 7
}

// round 5
// speedup vs baseline: 1.8055x; 1.0241x over previous
#include <cuda_runtime.h>
#include <math.h>

#define V 50257
#define E 1024
#define H 1024
#define L 52

#define OUT_BLOCKS 786   /* 786 blocks * 8 warps * 8 rows = 50304 >= V */

// ---- device scratch (no allocs allowed) ----
__device__ float g_emb[H];          // final emb (combined in k_attn_logits)
__device__ float g_emb_p[2 * H];    // emb partials (K-split)
__device__ float g_attn[H];
__device__ float g_x_p[2 * H];      // comb partials (K-split)
__device__ float g_alog[L];
__device__ float g_gi[3 * H];
__device__ float g_gh[3 * H];
__device__ float g_hnew[H];
__device__ float2 g_ms[OUT_BLOCKS]; // per-block online (max, sumexp)
__device__ int   g_cnt;             // zero-init; reset by last block each launch

__device__ __forceinline__ float warp_reduce_sum(float v) {
#pragma unroll
    for (int o = 16; o; o >>= 1) v += __shfl_down_sync(0xffffffffu, v, o);
    return v;
}

// online-softmax pair merge: (m,s) <- (m,s) (+) (m2,s2)
__device__ __forceinline__ void ms_merge(float& m, float& s, float m2, float s2) {
    if (s2 == 0.f) return;
    if (s == 0.f) { m = m2; s = s2; return; }
    float M = fmaxf(m, m2);
    s = s * expf(m - M) + s2 * expf(m2 - M);
    m = M;
}

// Dot of TWO weight rows vs shared vector over NF4 float4-chunks starting at
// chunk offset `off`, front-batched in groups of G (2*G LDG.128 in flight).
// Weight loads use __ldcs (streaming, no reuse).
template <int NF4, int G>
__device__ __forceinline__ void dot2rows(const float4* __restrict__ row0,
                                         const float4* __restrict__ row1,
                                         const float4* __restrict__ v4,
                                         int lane, int off,
                                         float& a0, float& a1) {
#pragma unroll
    for (int g = 0; g < NF4 / G; g++) {
        float4 xa[G], ya[G];
#pragma unroll
        for (int u = 0; u < G; u++) {
            int j = lane + (off + g * G + u) * 32;
            xa[u] = __ldcs(row0 + j);
            ya[u] = __ldcs(row1 + j);
        }
#pragma unroll
        for (int u = 0; u < G; u++) {
            int j = lane + (off + g * G + u) * 32;
            float4 c = v4[j];
            a0 += xa[u].x * c.x + xa[u].y * c.y + xa[u].z * c.z + xa[u].w * c.w;
            a1 += ya[u].x * c.x + ya[u].y * c.y + ya[u].z * c.z + ya[u].w * c.w;
        }
    }
}

// K1: emb partials. Grid 128 = 64 row-blocks x 2 K-splits.
// split sp handles E-half [sp*512, sp*512+512). Partials to g_emb_p[sp*H + r].
__global__ void __launch_bounds__(256, 2)
k_emb_linear(const int* __restrict__ token,
             const float* __restrict__ emb_table,
             const float* __restrict__ W) {
    __shared__ float sv[E / 2];
    int rb = blockIdx.x >> 1, sp = blockIdx.x & 1;
    const float* erow = emb_table + (size_t)token[0] * E + sp * (E / 2);
    for (int i = threadIdx.x; i < E / 2; i += blockDim.x) sv[i] = erow[i];
    __syncthreads();
    int warp = threadIdx.x >> 5, lane = threadIdx.x & 31;
    int r0 = (rb * 8 + warp) * 2;
    const float4* row0 = (const float4*)(W + (size_t)r0 * E + sp * (E / 2));
    const float4* row1 = (const float4*)(W + (size_t)(r0 + 1) * E + sp * (E / 2));
    float a0 = 0.f, a1 = 0.f;
    dot2rows<4, 4>(row0, row1, (const float4*)sv, lane, 0, a0, a1);
    a0 = warp_reduce_sum(a0);
    a1 = warp_reduce_sum(a1);
    if (lane == 0) {
        g_emb_p[sp * H + r0]     = a0;
        g_emb_p[sp * H + r0 + 1] = a1;
    }
}

// K2a: attention logits. Combines emb partials (+bias) while staging; block 0
// also persists combined emb to g_emb for k_comb.
__global__ void __launch_bounds__(256, 2)
k_attn_logits(const float* __restrict__ hidden,
              const float* __restrict__ linear_b,
              const float* __restrict__ attn_w,
              const float* __restrict__ attn_b) {
    __shared__ float sv[2 * H];
    for (int i = threadIdx.x; i < H; i += blockDim.x) {
        float e = g_emb_p[i] + g_emb_p[H + i] + linear_b[i];
        sv[i]     = e;
        sv[H + i] = hidden[i];
        if (blockIdx.x == 0) g_emb[i] = e;
    }
    __syncthreads();
    int warp = threadIdx.x >> 5, lane = threadIdx.x & 31;
    int r0 = (blockIdx.x * 8 + warp) * 2;
    if (r0 >= L) return;
    const float4* row0 = (const float4*)(attn_w + (size_t)r0 * 2 * H);
    const float4* row1 = (const float4*)(attn_w + (size_t)(r0 + 1) * 2 * H);
    float a0 = 0.f, a1 = 0.f;
    dot2rows<16, 8>(row0, row1, (const float4*)sv, lane, 0, a0, a1);
    a0 = warp_reduce_sum(a0);
    a1 = warp_reduce_sum(a1);
    if (lane == 0) {
        g_alog[r0]     = a0 + attn_b[r0];
        g_alog[r0 + 1] = a1 + attn_b[r0 + 1];
    }
}

// K2b: softmax over 52 logits (redundant per block) + attn_applied slice.
__global__ void __launch_bounds__(256)
k_attn_apply(const float* __restrict__ enc, float* __restrict__ out_attnw) {
    __shared__ float sw[L];
    if (threadIdx.x == 0) {
        float m = g_alog[0];
        for (int i = 1; i < L; i++) m = fmaxf(m, g_alog[i]);
        float s = 0.f;
        for (int i = 0; i < L; i++) { float e = expf(g_alog[i] - m); sw[i] = e; s += e; }
        float inv = 1.f / s;
        for (int i = 0; i < L; i++) sw[i] *= inv;
    }
    __syncthreads();
    int h = blockIdx.x * 256 + threadIdx.x;
    float acc = 0.f;
#pragma unroll
    for (int l = 0; l < L; l++) acc += sw[l] * enc[l * H + h];
    g_attn[h] = acc;
    if (blockIdx.x == 0 && threadIdx.x < L) out_attnw[threadIdx.x] = sw[threadIdx.x];
}

// K3: comb partials. Grid 128 = 64 row-blocks x 2 K-splits.
// sp=0: cols [0,H) vs emb;  sp=1: cols [H,2H) vs attn. No bias/relu here.
__global__ void __launch_bounds__(256, 2)
k_comb(const float* __restrict__ W) {
    __shared__ float sv[H];
    int rb = blockIdx.x >> 1, sp = blockIdx.x & 1;
    for (int i = threadIdx.x; i < H; i += blockDim.x)
        sv[i] = sp ? g_attn[i] : g_emb[i];
    __syncthreads();
    int warp = threadIdx.x >> 5, lane = threadIdx.x & 31;
    int r0 = (rb * 8 + warp) * 2;
    const float4* row0 = (const float4*)(W + (size_t)r0 * 2 * H + sp * H);
    const float4* row1 = (const float4*)(W + (size_t)(r0 + 1) * 2 * H + sp * H);
    float a0 = 0.f, a1 = 0.f;
    dot2rows<8, 8>(row0, row1, (const float4*)sv, lane, 0, a0, a1);
    a0 = warp_reduce_sum(a0);
    a1 = warp_reduce_sum(a1);
    if (lane == 0) {
        g_x_p[sp * H + r0]     = a0;
        g_x_p[sp * H + r0 + 1] = a1;
    }
}

// K4: gi/gh GEMVs (6144 row-tasks, 2/warp) + fused GRU combine in the
// last-finishing block. Combines comb partials (+bias+relu) while staging.
__global__ void __launch_bounds__(256, 2)
k_gru(const float* __restrict__ Wih, const float* __restrict__ Whh,
      const float* __restrict__ bih, const float* __restrict__ bhh,
      const float* __restrict__ comb_b,
      const float* __restrict__ hidden, float* __restrict__ out_h) {
    __shared__ float sx[H];
    __shared__ float sh[H];
    __shared__ int slast;
    for (int i = threadIdx.x; i < H; i += blockDim.x) {
        sx[i] = fmaxf(g_x_p[i] + g_x_p[H + i] + comb_b[i], 0.f);
        sh[i] = hidden[i];
    }
    __syncthreads();
    int warp = threadIdx.x >> 5, lane = threadIdx.x & 31;
    int t0 = (blockIdx.x * 8 + warp) * 2;          // 0..6142, never straddles 3H
    bool is_ih = (t0 < 3 * H);
    int r0 = is_ih ? t0 : t0 - 3 * H;
    const float* Wm = is_ih ? Wih : Whh;
    const float4* row0 = (const float4*)(Wm + (size_t)r0 * H);
    const float4* row1 = (const float4*)(Wm + (size_t)(r0 + 1) * H);
    const float4* v4 = (const float4*)(is_ih ? sx : sh);
    float a0 = 0.f, a1 = 0.f;
    dot2rows<8, 8>(row0, row1, v4, lane, 0, a0, a1);
    a0 = warp_reduce_sum(a0);
    a1 = warp_reduce_sum(a1);
    if (lane == 0) {
        if (is_ih) { g_gi[r0] = a0 + bih[r0]; g_gi[r0 + 1] = a1 + bih[r0 + 1]; }
        else       { g_gh[r0] = a0 + bhh[r0]; g_gh[r0 + 1] = a1 + bhh[r0 + 1]; }
    }
    // ---- last-block-done fused combine ----
    __syncthreads();
    __threadfence();
    if (threadIdx.x == 0) {
        int p = atomicAdd(&g_cnt, 1);
        slast = (p == (int)gridDim.x - 1);
    }
    __syncthreads();
    if (slast) {
        __threadfence();
        for (int i = threadIdx.x; i < H; i += blockDim.x) {
            float ir = g_gi[i], iz = g_gi[H + i], inn = g_gi[2 * H + i];
            float hr = g_gh[i], hz = g_gh[H + i], hn = g_gh[2 * H + i];
            float r = 1.f / (1.f + expf(-(ir + hr)));
            float z = 1.f / (1.f + expf(-(iz + hz)));
            float n = tanhf(inn + r * hn);
            float hv = (1.f - z) * n + z * sh[i];
            g_hnew[i] = hv;
            out_h[i] = hv;
        }
        if (threadIdx.x == 0) g_cnt = 0;   // reset for next replay
    }
}

// K5: logits = out_w @ h_new + out_b. 8 contiguous rows/warp in 4 pairs,
// group=4 front-batch (8 LDG.128 in flight), 4 blocks/SM residency.
__global__ void __launch_bounds__(256, 4)
k_out(const float* __restrict__ W, const float* __restrict__ b,
      float* __restrict__ out) {
    __shared__ float sv[H];
    __shared__ float wm[8], ws[8];
    for (int i = threadIdx.x; i < H; i += blockDim.x) sv[i] = g_hnew[i];
    __syncthreads();
    int warp = threadIdx.x >> 5, lane = threadIdx.x & 31;
    const float4* v4 = (const float4*)sv;
    int base = (blockIdx.x * 8 + warp) * 8;
    float m_w = -INFINITY, s_w = 0.f;
#pragma unroll
    for (int pr = 0; pr < 4; pr++) {
        int r0 = base + 2 * pr;
        if (r0 >= V) break;
        int r1c = min(r0 + 1, V - 1);              // clamp; duplicate read harmless
        const float4* row0 = (const float4*)(W + (size_t)r0 * H);
        const float4* row1 = (const float4*)(W + (size_t)r1c * H);
        float a0 = 0.f, a1 = 0.f;
        dot2rows<8, 4>(row0, row1, v4, lane, 0, a0, a1);
        a0 = warp_reduce_sum(a0);
        a1 = warp_reduce_sum(a1);
        if (lane == 0) {
            float l0 = a0 + b[r0];
            out[r0] = l0;
            ms_merge(m_w, s_w, l0, 1.f);
            if (r0 + 1 < V) {
                float l1 = a1 + b[r0 + 1];
                out[r0 + 1] = l1;
                ms_merge(m_w, s_w, l1, 1.f);
            }
        }
    }
    if (lane == 0) { wm[warp] = m_w; ws[warp] = s_w; }
    __syncthreads();
    if (threadIdx.x == 0) {
        float m = -INFINITY, s = 0.f;
#pragma unroll
        for (int w = 0; w < 8; w++) ms_merge(m, s, wm[w], ws[w]);
        g_ms[blockIdx.x] = make_float2(m, s);
    }
}

// K6: merge per-block (m,s) pairs -> lse, then subtract (log_softmax in place)
__global__ void __launch_bounds__(256)
k_sub(float* __restrict__ out) {
    __shared__ float sm[256], ss[256];
    float m = -INFINITY, s = 0.f;
    for (int i = threadIdx.x; i < OUT_BLOCKS; i += 256) {
        float2 p = g_ms[i];
        ms_merge(m, s, p.x, p.y);
    }
    sm[threadIdx.x] = m; ss[threadIdx.x] = s;
    __syncthreads();
    for (int st = 128; st; st >>= 1) {
        if (threadIdx.x < st) {
            float m1 = sm[threadIdx.x], s1 = ss[threadIdx.x];
            ms_merge(m1, s1, sm[threadIdx.x + st], ss[threadIdx.x + st]);
            sm[threadIdx.x] = m1; ss[threadIdx.x] = s1;
        }
        __syncthreads();
    }
    float lse = sm[0] + logf(ss[0]);
    for (int i = blockIdx.x * 256 + threadIdx.x; i < V; i += gridDim.x * 256)
        out[i] -= lse;
}

extern "C" void kernel_launch(void* const* d_in, const int* in_sizes, int n_in,
                              void* d_out, int out_size) {
    const int*   token     = (const int*)d_in[0];
    const float* hidden    = (const float*)d_in[1];
    const float* enc       = (const float*)d_in[2];
    const float* emb_table = (const float*)d_in[3];
    const float* linear_w  = (const float*)d_in[4];
    const float* linear_b  = (const float*)d_in[5];
    const float* attn_w    = (const float*)d_in[6];
    const float* attn_b    = (const float*)d_in[7];
    const float* comb_w    = (const float*)d_in[8];
    const float* comb_b    = (const float*)d_in[9];
    const float* gru_wih   = (const float*)d_in[10];
    const float* gru_whh   = (const float*)d_in[11];
    const float* gru_bih   = (const float*)d_in[12];
    const float* gru_bhh   = (const float*)d_in[13];
    const float* out_w     = (const float*)d_in[14];
    const float* out_b     = (const float*)d_in[15];

    float* out    = (float*)d_out;        // [0,V) log_probs
    float* out_h  = out + V;              // [V, V+H) h_new
    float* out_aw = out + V + H;          // [V+H, V+H+L) attn weights

    k_emb_linear<<<128, 256>>>(token, emb_table, linear_w);
    k_attn_logits<<<4, 256>>>(hidden, linear_b, attn_w, attn_b);
    k_attn_apply<<<4, 256>>>(enc, out_aw);
    k_comb<<<128, 256>>>(comb_w);
    k_gru<<<384, 256>>>(gru_wih, gru_whh, gru_bih, gru_bhh, comb_b, hidden, out_h);
    k_out<<<OUT_BLOCKS, 256>>>(out_w, out_b, out);
    k_sub<<<200, 256>>>(out);
}

// round 6
// speedup vs baseline: 1.8674x; 1.0343x over previous
#include <cuda_runtime.h>
#include <math.h>

#define V 50257
#define E 1024
#define H 1024
#define L 52

#define PRE_BLOCKS 148
#define PRE_WARPS (PRE_BLOCKS * 8)

#define OUT_CHUNK 16                       /* rows per warp in k_out */
#define OUT_BLOCKS 393                     /* ceil(V / (8*16)) */

// ---- device scratch (no allocs allowed) ----
__device__ float g_emb[H];
__device__ float g_attn[H];
__device__ float g_x_p[2 * H];      // comb partials (K-split)
__device__ float g_alog[L];
__device__ float g_gi[3 * H];
__device__ float g_gh[3 * H];
__device__ float g_hnew[H];
__device__ float2 g_ms[OUT_BLOCKS]; // per-block online (max, sumexp)
__device__ int   g_bar[8];          // phase barriers; reset by k_sub each launch

__device__ __forceinline__ float warp_reduce_sum(float v) {
#pragma unroll
    for (int o = 16; o; o >>= 1) v += __shfl_down_sync(0xffffffffu, v, o);
    return v;
}

// online-softmax pair merge
__device__ __forceinline__ void ms_merge(float& m, float& s, float m2, float s2) {
    if (s2 == 0.f) return;
    if (s == 0.f) { m = m2; s = s2; return; }
    float M = fmaxf(m, m2);
    s = s * expf(m - M) + s2 * expf(m2 - M);
    m = M;
}

// device-wide barrier: all PRE_BLOCKS co-resident blocks arrive, then proceed.
__device__ __forceinline__ void gbar(int ph) {
    __syncthreads();
    if (threadIdx.x == 0) {
        __threadfence();
        atomicAdd(&g_bar[ph], 1);
        volatile int* p = (volatile int*)&g_bar[ph];
        while (*p < PRE_BLOCKS) { __nanosleep(64); }
        __threadfence();
    }
    __syncthreads();
}

// Dot of TWO weight rows vs smem vector over NF4 float4-chunks,
// front-batched in groups of G (2*G LDG.128 in flight). __ldcs weights.
template <int NF4, int G>
__device__ __forceinline__ void dot2rows(const float4* __restrict__ row0,
                                         const float4* __restrict__ row1,
                                         const float4* __restrict__ v4,
                                         int lane, float& a0, float& a1) {
#pragma unroll
    for (int g = 0; g < NF4 / G; g++) {
        float4 xa[G], ya[G];
#pragma unroll
        for (int u = 0; u < G; u++) {
            int j = lane + (g * G + u) * 32;
            xa[u] = __ldcs(row0 + j);
            ya[u] = __ldcs(row1 + j);
        }
#pragma unroll
        for (int u = 0; u < G; u++) {
            int j = lane + (g * G + u) * 32;
            float4 c = v4[j];
            a0 += xa[u].x * c.x + xa[u].y * c.y + xa[u].z * c.z + xa[u].w * c.w;
            a1 += ya[u].x * c.x + ya[u].y * c.y + ya[u].z * c.z + ya[u].w * c.w;
        }
    }
}

// ============================================================================
// K_PRE: persistent kernel covering everything before the vocab projection.
// Phases (separated by device-wide barriers, all 148 blocks co-resident):
//  0: emb = linear_w @ emb_row + b  (512 pair-tasks, len E)
//     gh  = gru_whh @ h0 + bhh     (1536 pair-tasks, len H)   [independent]
//  1: attn logits (26 pair-tasks, len 2H)
//  2: softmax(52) + attn_applied (4 blocks x 256 cols)
//  3: comb partials, K-split      (1024 tasks, len H)
//  4: gi = gru_wih @ x + bih      (1536 pair-tasks, len H)
//  5: GRU combine -> h_new        (block 0)
// ============================================================================
__global__ void __launch_bounds__(256, 1)
k_pre(const int* __restrict__ token, const float* __restrict__ hidden,
      const float* __restrict__ enc, const float* __restrict__ emb_table,
      const float* __restrict__ linear_w, const float* __restrict__ linear_b,
      const float* __restrict__ attn_w, const float* __restrict__ attn_b,
      const float* __restrict__ comb_w, const float* __restrict__ comb_b,
      const float* __restrict__ gru_wih, const float* __restrict__ gru_whh,
      const float* __restrict__ gru_bih, const float* __restrict__ gru_bhh,
      float* __restrict__ out_h, float* __restrict__ out_aw) {
    __shared__ float svec[2 * H];
    __shared__ float sw[L];
    const int tid = threadIdx.x;
    const int warp = tid >> 5, lane = tid & 31;
    const int wgid = blockIdx.x * 8 + warp;
    const float4* v4 = (const float4*)svec;

    // ---- stage 0: svec = [emb_table[token], hidden] ----
    const float* erow = emb_table + (size_t)token[0] * E;
    for (int i = tid; i < H; i += 256) {
        svec[i]     = erow[i];
        svec[H + i] = hidden[i];
    }
    __syncthreads();

    // ---- phase 0: emb (tasks 0..511) + gh (tasks 512..2047) ----
    for (int t = wgid; t < 2048; t += PRE_WARPS) {
        if (t < 512) {
            int r0 = t * 2;
            const float4* row0 = (const float4*)(linear_w + (size_t)r0 * E);
            const float4* row1 = (const float4*)(linear_w + (size_t)(r0 + 1) * E);
            float a0 = 0.f, a1 = 0.f;
            dot2rows<8, 8>(row0, row1, v4, lane, a0, a1);
            a0 = warp_reduce_sum(a0);
            a1 = warp_reduce_sum(a1);
            if (lane == 0) {
                g_emb[r0]     = a0 + linear_b[r0];
                g_emb[r0 + 1] = a1 + linear_b[r0 + 1];
            }
        } else {
            int r0 = (t - 512) * 2;
            const float4* row0 = (const float4*)(gru_whh + (size_t)r0 * H);
            const float4* row1 = (const float4*)(gru_whh + (size_t)(r0 + 1) * H);
            float a0 = 0.f, a1 = 0.f;
            dot2rows<8, 8>(row0, row1, v4 + H / 4, lane, a0, a1);
            a0 = warp_reduce_sum(a0);
            a1 = warp_reduce_sum(a1);
            if (lane == 0) {
                g_gh[r0]     = a0 + gru_bhh[r0];
                g_gh[r0 + 1] = a1 + gru_bhh[r0 + 1];
            }
        }
    }
    gbar(0);

    // ---- stage 1: svec[0:H] = final emb (hidden remains at [H:2H]) ----
    for (int i = tid; i < H; i += 256) svec[i] = g_emb[i];
    __syncthreads();

    // ---- phase 1: attention logits (26 pair-tasks over warps 0..25) ----
    if (wgid < 26) {
        int r0 = wgid * 2;
        const float4* row0 = (const float4*)(attn_w + (size_t)r0 * 2 * H);
        const float4* row1 = (const float4*)(attn_w + (size_t)(r0 + 1) * 2 * H);
        float a0 = 0.f, a1 = 0.f;
        dot2rows<16, 8>(row0, row1, v4, lane, a0, a1);
        a0 = warp_reduce_sum(a0);
        a1 = warp_reduce_sum(a1);
        if (lane == 0) {
            g_alog[r0]     = a0 + attn_b[r0];
            g_alog[r0 + 1] = a1 + attn_b[r0 + 1];
        }
    }
    gbar(1);

    // ---- phase 2: softmax(52) redundantly in blocks 0..3, then apply ----
    if (blockIdx.x < 4) {
        if (tid == 0) {
            float m = g_alog[0];
            for (int i = 1; i < L; i++) m = fmaxf(m, g_alog[i]);
            float s = 0.f;
            for (int i = 0; i < L; i++) { float e = expf(g_alog[i] - m); sw[i] = e; s += e; }
            float inv = 1.f / s;
            for (int i = 0; i < L; i++) sw[i] *= inv;
        }
        __syncthreads();
        int h = blockIdx.x * 256 + tid;
        float acc = 0.f;
#pragma unroll
        for (int l = 0; l < L; l++) acc += sw[l] * enc[l * H + h];
        g_attn[h] = acc;
        if (blockIdx.x == 0 && tid < L) out_aw[tid] = sw[tid];
    }
    gbar(2);

    // ---- stage 3: svec[H:2H] = attn_applied (emb stays in [0:H]) ----
    for (int i = tid; i < H; i += 256) svec[H + i] = g_attn[i];
    __syncthreads();

    // ---- phase 3: comb partials, K-split (1024 tasks: pair = t>>1, sp = t&1) ----
    for (int t = wgid; t < 1024; t += PRE_WARPS) {
        int r0 = (t >> 1) * 2, sp = t & 1;
        const float4* row0 = (const float4*)(comb_w + (size_t)r0 * 2 * H + sp * H);
        const float4* row1 = (const float4*)(comb_w + (size_t)(r0 + 1) * 2 * H + sp * H);
        float a0 = 0.f, a1 = 0.f;
        dot2rows<8, 8>(row0, row1, v4 + sp * (H / 4), lane, a0, a1);
        a0 = warp_reduce_sum(a0);
        a1 = warp_reduce_sum(a1);
        if (lane == 0) {
            g_x_p[sp * H + r0]     = a0;
            g_x_p[sp * H + r0 + 1] = a1;
        }
    }
    gbar(3);

    // ---- stage 4: svec[0:H] = x = relu(partials + comb_b) ----
    for (int i = tid; i < H; i += 256)
        svec[i] = fmaxf(g_x_p[i] + g_x_p[H + i] + comb_b[i], 0.f);
    __syncthreads();

    // ---- phase 4: gi = gru_wih @ x + bih (1536 pair-tasks) ----
    for (int t = wgid; t < 1536; t += PRE_WARPS) {
        int r0 = t * 2;
        const float4* row0 = (const float4*)(gru_wih + (size_t)r0 * H);
        const float4* row1 = (const float4*)(gru_wih + (size_t)(r0 + 1) * H);
        float a0 = 0.f, a1 = 0.f;
        dot2rows<8, 8>(row0, row1, v4, lane, a0, a1);
        a0 = warp_reduce_sum(a0);
        a1 = warp_reduce_sum(a1);
        if (lane == 0) {
            g_gi[r0]     = a0 + gru_bih[r0];
            g_gi[r0 + 1] = a1 + gru_bih[r0 + 1];
        }
    }
    gbar(4);

    // ---- phase 5: GRU combine -> h_new (block 0 only) ----
    if (blockIdx.x == 0) {
        for (int i = tid; i < H; i += 256) {
            float ir = g_gi[i], iz = g_gi[H + i], inn = g_gi[2 * H + i];
            float hr = g_gh[i], hz = g_gh[H + i], hn = g_gh[2 * H + i];
            float r = 1.f / (1.f + expf(-(ir + hr)));
            float z = 1.f / (1.f + expf(-(iz + hz)));
            float n = tanhf(inn + r * hn);
            float hv = (1.f - z) * n + z * hidden[i];
            g_hnew[i] = hv;
            out_h[i] = hv;
        }
    }
}

// ============================================================================
// K_OUT: logits = out_w @ h_new + out_b. 16 contiguous rows/warp (8 pairs),
// single balanced wave (393 blocks, 3 blocks/SM). Emits (max,sumexp)/block.
// ============================================================================
__global__ void __launch_bounds__(256, 3)
k_out(const float* __restrict__ W, const float* __restrict__ b,
      float* __restrict__ out) {
    __shared__ float sv[H];
    __shared__ float wm[8], ws[8];
    for (int i = threadIdx.x; i < H; i += 256) sv[i] = g_hnew[i];
    __syncthreads();
    int warp = threadIdx.x >> 5, lane = threadIdx.x & 31;
    const float4* v4 = (const float4*)sv;
    int base = (blockIdx.x * 8 + warp) * OUT_CHUNK;
    float m_w = -INFINITY, s_w = 0.f;
#pragma unroll
    for (int pr = 0; pr < OUT_CHUNK / 2; pr++) {
        int r0 = base + 2 * pr;
        if (r0 >= V) break;
        int r1c = min(r0 + 1, V - 1);              // clamp; duplicate read harmless
        const float4* row0 = (const float4*)(W + (size_t)r0 * H);
        const float4* row1 = (const float4*)(W + (size_t)r1c * H);
        float a0 = 0.f, a1 = 0.f;
        dot2rows<8, 4>(row0, row1, v4, lane, a0, a1);
        a0 = warp_reduce_sum(a0);
        a1 = warp_reduce_sum(a1);
        if (lane == 0) {
            float l0 = a0 + b[r0];
            out[r0] = l0;
            ms_merge(m_w, s_w, l0, 1.f);
            if (r0 + 1 < V) {
                float l1 = a1 + b[r0 + 1];
                out[r0 + 1] = l1;
                ms_merge(m_w, s_w, l1, 1.f);
            }
        }
    }
    if (lane == 0) { wm[warp] = m_w; ws[warp] = s_w; }
    __syncthreads();
    if (threadIdx.x == 0) {
        float m = -INFINITY, s = 0.f;
#pragma unroll
        for (int w = 0; w < 8; w++) ms_merge(m, s, wm[w], ws[w]);
        g_ms[blockIdx.x] = make_float2(m, s);
    }
}

// K_SUB: merge per-block (m,s) -> lse, subtract in place; reset barriers.
__global__ void __launch_bounds__(256)
k_sub(float* __restrict__ out) {
    if (blockIdx.x == 0 && threadIdx.x < 8) g_bar[threadIdx.x] = 0;  // next replay
    __shared__ float sm[256], ss[256];
    float m = -INFINITY, s = 0.f;
    for (int i = threadIdx.x; i < OUT_BLOCKS; i += 256) {
        float2 p = g_ms[i];
        ms_merge(m, s, p.x, p.y);
    }
    sm[threadIdx.x] = m; ss[threadIdx.x] = s;
    __syncthreads();
    for (int st = 128; st; st >>= 1) {
        if (threadIdx.x < st) {
            float m1 = sm[threadIdx.x], s1 = ss[threadIdx.x];
            ms_merge(m1, s1, sm[threadIdx.x + st], ss[threadIdx.x + st]);
            sm[threadIdx.x] = m1; ss[threadIdx.x] = s1;
        }
        __syncthreads();
    }
    float lse = sm[0] + logf(ss[0]);
    for (int i = blockIdx.x * 256 + threadIdx.x; i < V; i += gridDim.x * 256)
        out[i] -= lse;
}

extern "C" void kernel_launch(void* const* d_in, const int* in_sizes, int n_in,
                              void* d_out, int out_size) {
    const int*   token     = (const int*)d_in[0];
    const float* hidden    = (const float*)d_in[1];
    const float* enc       = (const float*)d_in[2];
    const float* emb_table = (const float*)d_in[3];
    const float* linear_w  = (const float*)d_in[4];
    const float* linear_b  = (const float*)d_in[5];
    const float* attn_w    = (const float*)d_in[6];
    const float* attn_b    = (const float*)d_in[7];
    const float* comb_w    = (const float*)d_in[8];
    const float* comb_b    = (const float*)d_in[9];
    const float* gru_wih   = (const float*)d_in[10];
    const float* gru_whh   = (const float*)d_in[11];
    const float* gru_bih   = (const float*)d_in[12];
    const float* gru_bhh   = (const float*)d_in[13];
    const float* out_w     = (const float*)d_in[14];
    const float* out_b     = (const float*)d_in[15];

    float* out    = (float*)d_out;        // [0,V) log_probs
    float* out_h  = out + V;              // [V, V+H) h_new
    float* out_aw = out + V + H;          // [V+H, V+H+L) attn weights

    k_pre<<<PRE_BLOCKS, 256>>>(token, hidden, enc, emb_table,
                               linear_w, linear_b, attn_w, attn_b,
                               comb_w, comb_b, gru_wih, gru_whh,
                               gru_bih, gru_bhh, out_h, out_aw);
    k_out<<<OUT_BLOCKS, 256>>>(out_w, out_b, out);
    k_sub<<<200, 256>>>(out);
}